// round 2
// baseline (speedup 1.0000x reference)
#include <cuda_runtime.h>
#include <math.h>

// Problem constants
#define BB   2
#define TT   128
#define DD   256
#define HH   8
#define FF   64
#define CC   512
#define TE   512   // time embed dim

// Scratch: temb_emb[b,t,c] = temb @ w_time^T + b_time   (512 KB)
__device__ float g_temb_emb[BB * TT * CC];

// ---------------------------------------------------------------------------
// packed fp32x2 helpers (Blackwell dual-lane fp32 pipe; PTX-only path)
// ---------------------------------------------------------------------------
__device__ __forceinline__ unsigned long long pk2(float lo, float hi) {
    unsigned long long r;
    asm("mov.b64 %0, {%1, %2};" : "=l"(r) : "f"(lo), "f"(hi));
    return r;
}
__device__ __forceinline__ void fma2(unsigned long long &d,
                                     unsigned long long a,
                                     unsigned long long b) {
    asm("fma.rn.f32x2 %0, %1, %2, %0;" : "+l"(d) : "l"(a), "l"(b));
}
__device__ __forceinline__ void add2(unsigned long long &d, unsigned long long a) {
    asm("add.rn.f32x2 %0, %0, %1;" : "+l"(d) : "l"(a));
}

// ---------------------------------------------------------------------------
// Kernel 1: temb_emb[row, c] = b_time[c] + sum_k temb[row,k] * w_time[c,k]
// rows = B*T = 256, C = 512.  Tiled 32x64 (rows x cols), 16x16 threads,
// 2x4 microtile.  64 CTAs.
// ---------------------------------------------------------------------------
__global__ void __launch_bounds__(256) temb_kernel(
    const float* __restrict__ temb,
    const float* __restrict__ w_time,
    const float* __restrict__ b_time)
{
    __shared__ float As2[16][36];   // [k][row]
    __shared__ float Bs2[16][68];   // [k][col]

    const int tx = threadIdx.x, ty = threadIdx.y;
    const int tid = ty * 16 + tx;
    const int c0 = blockIdx.x * 64;
    const int r0 = blockIdx.y * 32;

    float acc[2][4];
#pragma unroll
    for (int i = 0; i < 2; i++)
#pragma unroll
        for (int j = 0; j < 4; j++) acc[i][j] = 0.f;

    for (int kt = 0; kt < TE; kt += 16) {
        const int kk = tid & 15;
        const int l0 = tid >> 4;
#pragma unroll
        for (int p = 0; p < 2; p++) {
            const int l = l0 + p * 16;
            As2[kk][l] = temb[(r0 + l) * TE + kt + kk];
        }
#pragma unroll
        for (int p = 0; p < 4; p++) {
            const int l = l0 + p * 16;
            Bs2[kk][l] = w_time[(c0 + l) * TE + kt + kk];
        }
        __syncthreads();
#pragma unroll
        for (int k = 0; k < 16; k++) {
            const float2 a = *(const float2*)&As2[k][ty * 2];
            const float4 w = *(const float4*)&Bs2[k][tx * 4];
            acc[0][0] += a.x * w.x; acc[0][1] += a.x * w.y; acc[0][2] += a.x * w.z; acc[0][3] += a.x * w.w;
            acc[1][0] += a.y * w.x; acc[1][1] += a.y * w.y; acc[1][2] += a.y * w.z; acc[1][3] += a.y * w.w;
        }
        __syncthreads();
    }

    const float4 bt = *(const float4*)&b_time[c0 + tx * 4];
#pragma unroll
    for (int i = 0; i < 2; i++) {
        float4 v;
        v.x = acc[i][0] + bt.x;
        v.y = acc[i][1] + bt.y;
        v.z = acc[i][2] + bt.z;
        v.w = acc[i][3] + bt.w;
        *(float4*)&g_temb_emb[(r0 + ty * 2 + i) * CC + c0 + tx * 4] = v;
    }
}

// ---------------------------------------------------------------------------
// Kernel 2: fused per-(b,t,h) pipeline.
//   emb[s,c]   = temb_emb[b,t,c] + pdf(s) . w_dist[c] + b_dist[c]
//   R[s,f]     = sum_c silu(emb[s,c]) * w_out[h*64+f, c] + b_out[h*64+f]
//   out[d,s]   = sum_f qk[b,d,h,t,f] * R[s,f]
// 512 threads, packed f32x2 FMA microkernels.
// ---------------------------------------------------------------------------

// dynamic smem layout (float offsets)
#define OF_PDF0  0
#define OF_PDF1  128
#define OF_PDF2  256
#define OF_TCOMB 384      // temb_emb(+b_dist) for this (b,t): 512
#define OF_WD0   896
#define OF_WD1   1408
#define OF_WD2   1920
#define OF_AS    2432     // silu tile [64][128]
#define OF_BSD   10624    // duplicated w_out tile [64][66] float2 (8448 floats)
#define OF_QS    19072    // qk tile [64][260]
#define OF_RS    35712    // R tile  [64][132]
#define SMEM_FLOATS 44160
#define SMEM_BYTES  (SMEM_FLOATS * 4)

__global__ void __launch_bounds__(512, 1) fused_kernel(
    const float* __restrict__ qk,
    const float* __restrict__ pdist,
    const float* __restrict__ w_dist,
    const float* __restrict__ b_dist,
    const float* __restrict__ w_out,
    const float* __restrict__ b_out,
    float* __restrict__ out)
{
    extern __shared__ float sm[];
    float*  pdf0  = sm + OF_PDF0;
    float*  pdf1  = sm + OF_PDF1;
    float*  pdf2  = sm + OF_PDF2;
    float*  tcomb = sm + OF_TCOMB;
    float*  wd0   = sm + OF_WD0;
    float*  wd1   = sm + OF_WD1;
    float*  wd2   = sm + OF_WD2;
    float*  As    = sm + OF_AS;
    float2* Bsd   = (float2*)(sm + OF_BSD);
    float*  Qs    = sm + OF_QS;
    float*  Rs    = sm + OF_RS;

    const int tid = threadIdx.x;
    const int bx  = blockIdx.x;
    const int h   = bx % HH;
    const int t   = (bx / HH) % TT;
    const int b   = bx / (HH * TT);

    // ---- distance features for this (b,t) row ----
    if (tid < 128) {
        const float p = pdist[(b * TT + t) * TT + tid];
        pdf0[tid] = log1pf(fmaxf(p, 0.f));
        pdf1[tid] = log1pf(fmaxf(-p, 0.f));
        pdf2[tid] = (p == 0.f) ? 1.f : 0.f;
    }
    // ---- per-channel constants: temb_emb + b_dist, and w_dist columns ----
    {
        const int c = tid;  // 512 threads == C
        tcomb[c] = g_temb_emb[(b * TT + t) * CC + c] + b_dist[c];
        wd0[c] = w_dist[c * 3 + 0];
        wd1[c] = w_dist[c * 3 + 1];
        wd2[c] = w_dist[c * 3 + 2];
    }
    // ---- Qs[f][d] = qk[b,d,h,t,f]  (transposed load, coalesced LDG) ----
    {
        const int f  = tid & 63;
        const int d0 = tid >> 6;  // 0..7
#pragma unroll 8
        for (int d = d0; d < DD; d += 8) {
            Qs[f * 260 + d] =
                qk[(((size_t)(b * DD + d) * HH + h) * TT + t) * FF + f];
        }
    }
    __syncthreads();

    // =========================== GEMM1 =====================================
    // R[s, f] = sum_c silu(emb[s,c]) * w_out[h*64+f, c]
    // thread tile: 4 s (2 f32x2 pairs) x 4 f.  fg = tid%16 (f), sg = tid/16 (s)
    const int fg = tid & 15;
    const int sg = tid >> 4;

    unsigned long long acc1[2][4];
#pragma unroll
    for (int i = 0; i < 2; i++)
#pragma unroll
        for (int j = 0; j < 4; j++) acc1[i][j] = 0ull;

    const float* wrow = w_out + (size_t)(h * FF) * CC;

    for (int kt = 0; kt < CC; kt += 64) {
        // fill silu tile As[kk][s]
        {
            const int s  = tid & 127;
            const int k0 = tid >> 7;  // 0..3
            const float p0 = pdf0[s], p1 = pdf1[s], p2 = pdf2[s];
#pragma unroll
            for (int kk = k0; kk < 64; kk += 4) {
                const int c = kt + kk;
                const float x = tcomb[c] + p0 * wd0[c] + p1 * wd1[c] + p2 * wd2[c];
                const float sig = 1.f / (1.f + __expf(-x));
                As[kk * 128 + s] = x * sig;
            }
        }
        // fill duplicated w_out tile Bsd[kk][o] = (w, w)
        {
            const int kk = tid & 63;
            const int o0 = tid >> 6;  // 0..7
#pragma unroll
            for (int o = o0; o < 64; o += 8) {
                const float w = wrow[(size_t)o * CC + kt + kk];
                Bsd[kk * 66 + o] = make_float2(w, w);
            }
        }
        __syncthreads();

#pragma unroll 4
        for (int k = 0; k < 64; k++) {
            const ulonglong2 av  = *(const ulonglong2*)(As + k * 128 + (sg << 2));
            const ulonglong2 b01 = *(const ulonglong2*)(Bsd + k * 66 + (fg << 2));
            const ulonglong2 b23 = *(const ulonglong2*)(Bsd + k * 66 + (fg << 2) + 2);
            fma2(acc1[0][0], av.x, b01.x);
            fma2(acc1[0][1], av.x, b01.y);
            fma2(acc1[0][2], av.x, b23.x);
            fma2(acc1[0][3], av.x, b23.y);
            fma2(acc1[1][0], av.y, b01.x);
            fma2(acc1[1][1], av.y, b01.y);
            fma2(acc1[1][2], av.y, b23.x);
            fma2(acc1[1][3], av.y, b23.y);
        }
        __syncthreads();
    }

    // ---- write R to smem (transposed: Rs[f][s]) with +b_out ----
    {
#pragma unroll
        for (int j = 0; j < 4; j++) {
            const int f = (fg << 2) + j;
            const float bo = b_out[h * FF + f];
            const unsigned long long bod = pk2(bo, bo);
            unsigned long long v0 = acc1[0][j];
            unsigned long long v1 = acc1[1][j];
            add2(v0, bod);
            add2(v1, bod);
            *(unsigned long long*)(Rs + f * 132 + (sg << 2))     = v0;
            *(unsigned long long*)(Rs + f * 132 + (sg << 2) + 2) = v1;
        }
    }
    __syncthreads();

    // =========================== GEMM2 =====================================
    // out[d, s] = sum_f Qs[f][d] * Rs[f][s]
    // thread tile: 4 d x 8 s (4 f32x2 pairs).  sg2 = tid%16 (s), dg2 = tid/16 (d)
    const int sg2 = tid & 15;
    const int dg2 = tid >> 4;  // 0..31

#pragma unroll 1
    for (int dch = 0; dch < DD; dch += 128) {
        unsigned long long acc2[4][4];
#pragma unroll
        for (int i = 0; i < 4; i++)
#pragma unroll
            for (int j = 0; j < 4; j++) acc2[i][j] = 0ull;

#pragma unroll 4
        for (int f = 0; f < 64; f++) {
            const float4 a = *(const float4*)(Qs + f * 260 + dch + (dg2 << 2));
            const ulonglong2 bA = *(const ulonglong2*)(Rs + f * 132 + (sg2 << 3));
            const ulonglong2 bB = *(const ulonglong2*)(Rs + f * 132 + (sg2 << 3) + 4);
            const unsigned long long a0 = pk2(a.x, a.x);
            const unsigned long long a1 = pk2(a.y, a.y);
            const unsigned long long a2 = pk2(a.z, a.z);
            const unsigned long long a3 = pk2(a.w, a.w);
            fma2(acc2[0][0], a0, bA.x); fma2(acc2[0][1], a0, bA.y);
            fma2(acc2[0][2], a0, bB.x); fma2(acc2[0][3], a0, bB.y);
            fma2(acc2[1][0], a1, bA.x); fma2(acc2[1][1], a1, bA.y);
            fma2(acc2[1][2], a1, bB.x); fma2(acc2[1][3], a1, bB.y);
            fma2(acc2[2][0], a2, bA.x); fma2(acc2[2][1], a2, bA.y);
            fma2(acc2[2][2], a2, bB.x); fma2(acc2[2][3], a2, bB.y);
            fma2(acc2[3][0], a3, bA.x); fma2(acc2[3][1], a3, bA.y);
            fma2(acc2[3][2], a3, bB.x); fma2(acc2[3][3], a3, bB.y);
        }

        // coalesced 2x16B stores per d-row: out[b, d, h, t, s0..s0+7]
#pragma unroll
        for (int i = 0; i < 4; i++) {
            const int d = dch + (dg2 << 2) + i;
            float* optr = out +
                (((size_t)(b * DD + d) * HH + h) * TT + t) * TT + (sg2 << 3);
            ulonglong2 v0; v0.x = acc2[i][0]; v0.y = acc2[i][1];
            ulonglong2 v1; v1.x = acc2[i][2]; v1.y = acc2[i][3];
            *(ulonglong2*)(optr)     = v0;
            *(ulonglong2*)(optr + 4) = v1;
        }
    }
}

// ---------------------------------------------------------------------------
extern "C" void kernel_launch(void* const* d_in, const int* in_sizes, int n_in,
                              void* d_out, int out_size)
{
    const float* qk      = (const float*)d_in[0];
    const float* pdist   = (const float*)d_in[1];
    const float* temb    = (const float*)d_in[2];
    const float* w_dist  = (const float*)d_in[3];
    const float* b_dist  = (const float*)d_in[4];
    const float* w_time  = (const float*)d_in[5];
    const float* b_time  = (const float*)d_in[6];
    const float* w_out   = (const float*)d_in[7];
    const float* b_out   = (const float*)d_in[8];
    float* out = (float*)d_out;

    // temb_emb precompute: 8 c-tiles x 8 row-tiles (64 CTAs)
    dim3 g1(CC / 64, (BB * TT) / 32);
    dim3 t1(16, 16);
    temb_kernel<<<g1, t1>>>(temb, w_time, b_time);

    cudaFuncSetAttribute(fused_kernel,
                         cudaFuncAttributeMaxDynamicSharedMemorySize, SMEM_BYTES);
    fused_kernel<<<BB * TT * HH, 512, SMEM_BYTES>>>(
        qk, pdist, w_dist, b_dist, w_out, b_out, out);
}

// round 3
// speedup vs baseline: 2.3282x; 2.3282x over previous
#include <cuda_runtime.h>
#include <math.h>

// Problem constants
#define BB   2
#define TT   128
#define DD   256
#define HH   8
#define FF   64
#define CC   512
#define TE   512

// Scratch: temb_emb[b,t,c] = temb @ w_time^T + b_time   (512 KB)
__device__ float g_temb_emb[BB * TT * CC];

// ---------------------------------------------------------------------------
// packed fp32x2 helpers
// ---------------------------------------------------------------------------
__device__ __forceinline__ unsigned long long pk2(float lo, float hi) {
    unsigned long long r;
    asm("mov.b64 %0, {%1, %2};" : "=l"(r) : "f"(lo), "f"(hi));
    return r;
}
__device__ __forceinline__ void fma2(unsigned long long &d,
                                     unsigned long long a,
                                     unsigned long long b) {
    asm("fma.rn.f32x2 %0, %1, %2, %0;" : "+l"(d) : "l"(a), "l"(b));
}
__device__ __forceinline__ void add2(unsigned long long &d, unsigned long long a) {
    asm("add.rn.f32x2 %0, %0, %1;" : "+l"(d) : "l"(a));
}
__device__ __forceinline__ void upk2(unsigned long long v, float &lo, float &hi) {
    asm("mov.b64 {%0, %1}, %2;" : "=f"(lo), "=f"(hi) : "l"(v));
}

// ---------------------------------------------------------------------------
// Kernel 1: temb_emb = temb @ w_time^T + b_time   (unchanged, fast)
// ---------------------------------------------------------------------------
__global__ void __launch_bounds__(256) temb_kernel(
    const float* __restrict__ temb,
    const float* __restrict__ w_time,
    const float* __restrict__ b_time)
{
    __shared__ float As2[16][36];
    __shared__ float Bs2[16][68];

    const int tx = threadIdx.x, ty = threadIdx.y;
    const int tid = ty * 16 + tx;
    const int c0 = blockIdx.x * 64;
    const int r0 = blockIdx.y * 32;

    float acc[2][4];
#pragma unroll
    for (int i = 0; i < 2; i++)
#pragma unroll
        for (int j = 0; j < 4; j++) acc[i][j] = 0.f;

    for (int kt = 0; kt < TE; kt += 16) {
        const int kk = tid & 15;
        const int l0 = tid >> 4;
#pragma unroll
        for (int p = 0; p < 2; p++)
            As2[kk][l0 + p * 16] = temb[(r0 + l0 + p * 16) * TE + kt + kk];
#pragma unroll
        for (int p = 0; p < 4; p++)
            Bs2[kk][l0 + p * 16] = w_time[(c0 + l0 + p * 16) * TE + kt + kk];
        __syncthreads();
#pragma unroll
        for (int k = 0; k < 16; k++) {
            const float2 a = *(const float2*)&As2[k][ty * 2];
            const float4 w = *(const float4*)&Bs2[k][tx * 4];
            acc[0][0] += a.x * w.x; acc[0][1] += a.x * w.y; acc[0][2] += a.x * w.z; acc[0][3] += a.x * w.w;
            acc[1][0] += a.y * w.x; acc[1][1] += a.y * w.y; acc[1][2] += a.y * w.z; acc[1][3] += a.y * w.w;
        }
        __syncthreads();
    }

    const float4 bt = *(const float4*)&b_time[c0 + tx * 4];
#pragma unroll
    for (int i = 0; i < 2; i++) {
        float4 v;
        v.x = acc[i][0] + bt.x;
        v.y = acc[i][1] + bt.y;
        v.z = acc[i][2] + bt.z;
        v.w = acc[i][3] + bt.w;
        *(float4*)&g_temb_emb[(r0 + ty * 2 + i) * CC + c0 + tx * 4] = v;
    }
}

// ---------------------------------------------------------------------------
// Kernel 2: one CTA per (b, t, head-pair).  512 threads.
//   GEMM1: R[s, f2] = sum_c silu(emb[s,c]) * w_out[hp*128+f2, c]   (128x128x512)
//   GEMM2 (x2 heads): out[d, s] = sum_f qk[b,d,h,t,f] * R[s, hl*64+f]
// ---------------------------------------------------------------------------

// dynamic smem layout (float offsets)
#define OF_PDF0  0
#define OF_PDF1  128
#define OF_PDF2  256
#define OF_TCOMB 384
#define OF_WD0   896
#define OF_WD1   1408
#define OF_WD2   1920
#define OF_AS    2432      // [64][128]  silu tile       (phase 1, aliases RsT)
#define OF_BS    10624     // [64][132]  w_out tile      (phase 1, aliases RsT)
#define OF_RST   2432      // [128][132] R transposed    (phase 2)
#define OF_QS    19328     // [64][260]  qk tile         (phase 2)
#define SMEM_FLOATS 35968
#define SMEM_BYTES  (SMEM_FLOATS * 4)

__global__ void __launch_bounds__(512, 1) fused_kernel(
    const float* __restrict__ qk,
    const float* __restrict__ pdist,
    const float* __restrict__ w_dist,
    const float* __restrict__ b_dist,
    const float* __restrict__ w_out,
    const float* __restrict__ b_out,
    float* __restrict__ out)
{
    extern __shared__ float sm[];
    float* pdf0  = sm + OF_PDF0;
    float* pdf1  = sm + OF_PDF1;
    float* pdf2  = sm + OF_PDF2;
    float* tcomb = sm + OF_TCOMB;
    float* wd0   = sm + OF_WD0;
    float* wd1   = sm + OF_WD1;
    float* wd2   = sm + OF_WD2;
    float* As    = sm + OF_AS;
    float* Bs    = sm + OF_BS;
    float* RsT   = sm + OF_RST;
    float* Qs    = sm + OF_QS;

    const int tid = threadIdx.x;
    const int bx  = blockIdx.x;
    const int hp  = bx & 3;            // head pair 0..3
    const int t   = (bx >> 2) & 127;
    const int b   = bx >> 9;

    // ---- per-(b,t) constants ----
    if (tid < 128) {
        const float p = pdist[(b * TT + t) * TT + tid];
        pdf0[tid] = log1pf(fmaxf(p, 0.f));
        pdf1[tid] = log1pf(fmaxf(-p, 0.f));
        pdf2[tid] = (p == 0.f) ? 1.f : 0.f;
    }
    {
        const int c = tid;             // 512 threads == C
        tcomb[c] = g_temb_emb[(b * TT + t) * CC + c] + b_dist[c];
        wd0[c] = w_dist[c * 3 + 0];
        wd1[c] = w_dist[c * 3 + 1];
        wd2[c] = w_dist[c * 3 + 2];
    }

    // =========================== GEMM1 =====================================
    // thread tile: 16 s (8 f32x2 pairs) x 2 f.
    // fg = tid & 63 (f-group of 2), sg = tid >> 6 (s-group of 16).
    // warp = single sg x 32 fg  ->  A-loads are all-lane broadcast,
    //                               B-load is one contiguous LDS.64.
    const int fg = tid & 63;
    const int sg = tid >> 6;

    unsigned long long acc1[8][2];
#pragma unroll
    for (int p = 0; p < 8; p++) { acc1[p][0] = 0ull; acc1[p][1] = 0ull; }

    const int c4 = tid & 15;           // col quad for B fill
    const int oo = tid >> 4;           // row 0..31 for B fill
    const int ss = tid & 127;          // s for silu fill
    const int k0 = tid >> 7;           // 0..3

    for (int kt = 0; kt < CC; kt += 64) {
        __syncthreads();   // previous tile's readers done
        // prefetch w_out tile to regs (rows hp*128 .. +127, cols kt..kt+63)
        float4 bw[4];
#pragma unroll
        for (int q = 0; q < 4; q++)
            bw[q] = *(const float4*)(w_out +
                     (size_t)(hp * 128 + oo + q * 32) * CC + kt + c4 * 4);
        // silu tile As[kk][s]  (MUFU-heavy; overlaps the LDG latency above)
        {
            const float p0 = pdf0[ss], p1 = pdf1[ss], p2 = pdf2[ss];
#pragma unroll
            for (int kk = k0; kk < 64; kk += 4) {
                const int c = kt + kk;
                const float x = tcomb[c] + p0 * wd0[c] + p1 * wd1[c] + p2 * wd2[c];
                As[kk * 128 + ss] = __fdividef(x, 1.f + __expf(-x));
            }
        }
        // store w_out tile transposed: Bs[kk][f2]
#pragma unroll
        for (int q = 0; q < 4; q++) {
            Bs[(c4 * 4 + 0) * 132 + oo + q * 32] = bw[q].x;
            Bs[(c4 * 4 + 1) * 132 + oo + q * 32] = bw[q].y;
            Bs[(c4 * 4 + 2) * 132 + oo + q * 32] = bw[q].z;
            Bs[(c4 * 4 + 3) * 132 + oo + q * 32] = bw[q].w;
        }
        __syncthreads();

#pragma unroll 4
        for (int k = 0; k < 64; k++) {
            const float2 bf = *(const float2*)(Bs + k * 132 + fg * 2);
            const unsigned long long b0 = pk2(bf.x, bf.x);
            const unsigned long long b1 = pk2(bf.y, bf.y);
            const float* arow = As + k * 128 + sg * 16;
            const ulonglong2 a01 = *(const ulonglong2*)(arow);
            const ulonglong2 a23 = *(const ulonglong2*)(arow + 4);
            const ulonglong2 a45 = *(const ulonglong2*)(arow + 8);
            const ulonglong2 a67 = *(const ulonglong2*)(arow + 12);
            fma2(acc1[0][0], a01.x, b0); fma2(acc1[0][1], a01.x, b1);
            fma2(acc1[1][0], a01.y, b0); fma2(acc1[1][1], a01.y, b1);
            fma2(acc1[2][0], a23.x, b0); fma2(acc1[2][1], a23.x, b1);
            fma2(acc1[3][0], a23.y, b0); fma2(acc1[3][1], a23.y, b1);
            fma2(acc1[4][0], a45.x, b0); fma2(acc1[4][1], a45.x, b1);
            fma2(acc1[5][0], a45.y, b0); fma2(acc1[5][1], a45.y, b1);
            fma2(acc1[6][0], a67.x, b0); fma2(acc1[6][1], a67.x, b1);
            fma2(acc1[7][0], a67.y, b0); fma2(acc1[7][1], a67.y, b1);
        }
    }
    __syncthreads();   // As/Bs dead; safe to overwrite with RsT

    // ---- write R transposed to smem: RsT[f2][s], + b_out ----
#pragma unroll
    for (int j = 0; j < 2; j++) {
        const int f2 = fg * 2 + j;
        const float bo = b_out[hp * 128 + f2];
        const unsigned long long bod = pk2(bo, bo);
#pragma unroll
        for (int p = 0; p < 8; p++) add2(acc1[p][j], bod);
        float* rrow = RsT + f2 * 132 + sg * 16;
#pragma unroll
        for (int q = 0; q < 4; q++) {
            ulonglong2 v;
            v.x = acc1[2 * q][j];
            v.y = acc1[2 * q + 1][j];
            *(ulonglong2*)(rrow + 4 * q) = v;
        }
    }
    __syncthreads();

    // =========================== GEMM2 (per head) ==========================
    // thread tile: 16 d (8 f32x2 pairs) x 4 s.
    // sg2 = tid & 31 (s-group of 4), dg2 = tid >> 5 (d-group of 16).
    // warp = single dg2 x 32 sg2 -> Qs loads broadcast, RsT load contiguous.
    const int sg2 = tid & 31;
    const int dg2 = tid >> 5;
    const int fq  = tid & 15;          // f quad for Qs fill
    const int dl  = tid >> 4;          // d 0..31 for Qs fill

#pragma unroll 1
    for (int hl = 0; hl < 2; hl++) {
        const int h = hp * 2 + hl;
        // fill Qs[f][d] (transposed)
#pragma unroll
        for (int pass = 0; pass < 8; pass++) {
            const int d = dl + pass * 32;
            const float4 v = *(const float4*)(qk +
                (((size_t)(b * DD + d) * HH + h) * TT + t) * FF + fq * 4);
            Qs[(4 * fq + 0) * 260 + d] = v.x;
            Qs[(4 * fq + 1) * 260 + d] = v.y;
            Qs[(4 * fq + 2) * 260 + d] = v.z;
            Qs[(4 * fq + 3) * 260 + d] = v.w;
        }
        __syncthreads();

        unsigned long long acc2[8][4];
#pragma unroll
        for (int p = 0; p < 8; p++)
#pragma unroll
            for (int j = 0; j < 4; j++) acc2[p][j] = 0ull;

#pragma unroll 2
        for (int f = 0; f < 64; f++) {
            const float4 rv = *(const float4*)(RsT + (hl * 64 + f) * 132 + sg2 * 4);
            const unsigned long long r0 = pk2(rv.x, rv.x);
            const unsigned long long r1 = pk2(rv.y, rv.y);
            const unsigned long long r2 = pk2(rv.z, rv.z);
            const unsigned long long r3 = pk2(rv.w, rv.w);
            const float* qrow = Qs + f * 260 + dg2 * 16;
            const ulonglong2 qa = *(const ulonglong2*)(qrow);
            const ulonglong2 qb = *(const ulonglong2*)(qrow + 4);
            const ulonglong2 qc = *(const ulonglong2*)(qrow + 8);
            const ulonglong2 qd = *(const ulonglong2*)(qrow + 12);
            fma2(acc2[0][0], qa.x, r0); fma2(acc2[0][1], qa.x, r1);
            fma2(acc2[0][2], qa.x, r2); fma2(acc2[0][3], qa.x, r3);
            fma2(acc2[1][0], qa.y, r0); fma2(acc2[1][1], qa.y, r1);
            fma2(acc2[1][2], qa.y, r2); fma2(acc2[1][3], qa.y, r3);
            fma2(acc2[2][0], qb.x, r0); fma2(acc2[2][1], qb.x, r1);
            fma2(acc2[2][2], qb.x, r2); fma2(acc2[2][3], qb.x, r3);
            fma2(acc2[3][0], qb.y, r0); fma2(acc2[3][1], qb.y, r1);
            fma2(acc2[3][2], qb.y, r2); fma2(acc2[3][3], qb.y, r3);
            fma2(acc2[4][0], qc.x, r0); fma2(acc2[4][1], qc.x, r1);
            fma2(acc2[4][2], qc.x, r2); fma2(acc2[4][3], qc.x, r3);
            fma2(acc2[5][0], qc.y, r0); fma2(acc2[5][1], qc.y, r1);
            fma2(acc2[5][2], qc.y, r2); fma2(acc2[5][3], qc.y, r3);
            fma2(acc2[6][0], qd.x, r0); fma2(acc2[6][1], qd.x, r1);
            fma2(acc2[6][2], qd.x, r2); fma2(acc2[6][3], qd.x, r3);
            fma2(acc2[7][0], qd.y, r0); fma2(acc2[7][1], qd.y, r1);
            fma2(acc2[7][2], qd.y, r2); fma2(acc2[7][3], qd.y, r3);
        }

        // store: out[b, d, h, t, s0..s0+3], d-pairs unpacked
#pragma unroll
        for (int p = 0; p < 8; p++) {
            float lo0, hi0, lo1, hi1, lo2, hi2, lo3, hi3;
            upk2(acc2[p][0], lo0, hi0);
            upk2(acc2[p][1], lo1, hi1);
            upk2(acc2[p][2], lo2, hi2);
            upk2(acc2[p][3], lo3, hi3);
            const int d = dg2 * 16 + 2 * p;
            float* base = out +
                (((size_t)(b * DD + d) * HH + h) * TT + t) * TT + sg2 * 4;
            float4 vlo; vlo.x = lo0; vlo.y = lo1; vlo.z = lo2; vlo.w = lo3;
            float4 vhi; vhi.x = hi0; vhi.y = hi1; vhi.z = hi2; vhi.w = hi3;
            *(float4*)(base) = vlo;
            *(float4*)(base + (size_t)HH * TT * TT) = vhi;   // d+1
        }
        __syncthreads();   // before next head's Qs overwrite
    }
}

// ---------------------------------------------------------------------------
extern "C" void kernel_launch(void* const* d_in, const int* in_sizes, int n_in,
                              void* d_out, int out_size)
{
    const float* qk      = (const float*)d_in[0];
    const float* pdist   = (const float*)d_in[1];
    const float* temb    = (const float*)d_in[2];
    const float* w_dist  = (const float*)d_in[3];
    const float* b_dist  = (const float*)d_in[4];
    const float* w_time  = (const float*)d_in[5];
    const float* b_time  = (const float*)d_in[6];
    const float* w_out   = (const float*)d_in[7];
    const float* b_out   = (const float*)d_in[8];
    float* out = (float*)d_out;

    dim3 g1(CC / 64, (BB * TT) / 32);
    dim3 t1(16, 16);
    temb_kernel<<<g1, t1>>>(temb, w_time, b_time);

    cudaFuncSetAttribute(fused_kernel,
                         cudaFuncAttributeMaxDynamicSharedMemorySize, SMEM_BYTES);
    fused_kernel<<<BB * TT * 4, 512, SMEM_BYTES>>>(
        qk, pdist, w_dist, b_dist, w_out, b_out, out);
}